// round 2
// baseline (speedup 1.0000x reference)
#include <cuda_runtime.h>
#include <math.h>

#define HIDDEN     2048
#define SEQ        4096
#define BATCH      8
#define NCHUNK     64
#define CHUNK      (SEQ / NCHUNK)      // 64 rows per chunk
#define TOTAL_RANK 16
#define ACTIVE_RANK 8
#define ADAPT_DIM  32
#define LN_EPS     1e-5f

// Scratch (no allocations allowed in kernel_launch)
__device__ float g_partial[BATCH * NCHUNK * HIDDEN];   // 4 MB
__device__ float g_pooled [BATCH * HIDDEN];
__device__ float g_x      [BATCH * ADAPT_DIM];
__device__ float g_M      [BATCH * TOTAL_RANK * TOTAL_RANK];

// ---------------------------------------------------------------------------
// Kernel 1: partial sums over S-chunks of hidden_states.
// grid = BATCH*NCHUNK (512) blocks, 512 threads; each thread owns 4 h-columns
// via float4, loops 64 s-rows. Fully coalesced 128B/warp.
// ---------------------------------------------------------------------------
__global__ __launch_bounds__(512) void k_partial(const float* __restrict__ hs) {
    int blk = blockIdx.x;
    int b   = blk >> 6;          // / NCHUNK
    int c   = blk & (NCHUNK - 1);
    int t   = threadIdx.x;       // 0..511, each handles float4 at h = 4t

    const float4* p = reinterpret_cast<const float4*>(
        hs + ((size_t)(b * SEQ + c * CHUNK)) * HIDDEN) + t;

    float4 acc = make_float4(0.f, 0.f, 0.f, 0.f);
#pragma unroll 8
    for (int i = 0; i < CHUNK; i++) {
        float4 v = p[(size_t)i * (HIDDEN / 4)];
        acc.x += v.x; acc.y += v.y; acc.z += v.z; acc.w += v.w;
    }
    reinterpret_cast<float4*>(g_partial + (size_t)blk * HIDDEN)[t] = acc;
}

// ---------------------------------------------------------------------------
// Kernel 1b: reduce NCHUNK partials -> pooled mean. 16384 threads, coalesced.
// ---------------------------------------------------------------------------
__global__ __launch_bounds__(512) void k_pool() {
    int idx = blockIdx.x * 512 + threadIdx.x;      // 0..16383
    int b   = idx >> 11;                            // / HIDDEN
    int h   = idx & (HIDDEN - 1);
    const float* p = g_partial + (size_t)b * NCHUNK * HIDDEN + h;
    float s = 0.f;
#pragma unroll 8
    for (int c = 0; c < NCHUNK; c++) s += p[(size_t)c * HIDDEN];
    g_pooled[idx] = s * (1.0f / SEQ);
}

// ---------------------------------------------------------------------------
// Kernel 2a: x[b,:] = pooled[b,:] @ W1   (2048x32 GEMV per batch)
// 8 blocks x 256 threads. Warp w covers h in [w*256, w*256+256), lane = column.
// W1[h*32+lane] is a coalesced 128B read per warp-step; pooled[h] broadcasts.
// ---------------------------------------------------------------------------
__global__ __launch_bounds__(256) void k_x(const float* __restrict__ W1) {
    int b = blockIdx.x;
    int w = threadIdx.x >> 5;
    int l = threadIdx.x & 31;
    const float* pooled = g_pooled + b * HIDDEN;

    float acc = 0.f;
    int h0 = w * 256;
#pragma unroll 4
    for (int i = 0; i < 256; i++) {
        int h = h0 + i;
        acc += pooled[h] * W1[h * ADAPT_DIM + l];
    }
    __shared__ float sm[8][ADAPT_DIM];
    sm[w][l] = acc;
    __syncthreads();
    if (w == 0) {
        float s = 0.f;
#pragma unroll
        for (int j = 0; j < 8; j++) s += sm[j][l];
        g_x[b * ADAPT_DIM + l] = s;
    }
}

// ---------------------------------------------------------------------------
// Kernel 2b: bias + LayerNorm + exact GELU + W2 + top-8 mask + bake M.
// One block, 8 warps (warp = batch), lane = adapt channel.
// ---------------------------------------------------------------------------
__global__ __launch_bounds__(256) void k_ctrl(
    const float* __restrict__ b1, const float* __restrict__ gamma,
    const float* __restrict__ beta, const float* __restrict__ W2,
    const float* __restrict__ b2, const float* __restrict__ ml,
    const float* __restrict__ rs)
{
    const unsigned FULL = 0xFFFFFFFFu;
    int b = threadIdx.x >> 5;
    int l = threadIdx.x & 31;

    float x = g_x[b * ADAPT_DIM + l] + b1[l];

    // LayerNorm over 32 lanes (population variance, like jnp.var)
    float mu = x;
#pragma unroll
    for (int o = 16; o; o >>= 1) mu += __shfl_xor_sync(FULL, mu, o);
    mu *= (1.0f / ADAPT_DIM);
    float d = x - mu;
    float v = d * d;
#pragma unroll
    for (int o = 16; o; o >>= 1) v += __shfl_xor_sync(FULL, v, o);
    v *= (1.0f / ADAPT_DIM);
    x = d * rsqrtf(v + LN_EPS) * gamma[l] + beta[l];

    // exact GELU: 0.5*x*(1+erf(x/sqrt(2)))
    x = 0.5f * x * (1.0f + erff(x * 0.70710678118654752f));

    // logits[r] = sum_a x[a] * W2[a,r]  via shuffle broadcast
    float acc = 0.f;
#pragma unroll
    for (int a = 0; a < ADAPT_DIM; a++) {
        float xa = __shfl_sync(FULL, x, a);
        if (l < TOTAL_RANK) acc += xa * W2[a * TOTAL_RANK + l];
    }
    float comb = (l < TOTAL_RANK) ? (acc + b2[l] + ml[l]) : -1e30f;

    // top-8 of 16 with lax.top_k tie semantics (stable: lower index wins)
    int cnt = 0;
#pragma unroll
    for (int j = 0; j < TOTAL_RANK; j++) {
        float cj = __shfl_sync(FULL, comb, j);
        if (l < TOTAL_RANK && (cj > comb || (cj == comb && j < l))) cnt++;
    }
    float factor = (l < TOTAL_RANK && cnt < ACTIVE_RANK) ? rs[l] : 0.f;

    // M[b][d][r] = factor[r] * H[d][r], H[d][r] = (-1)^popc(d&r) / 32
    if (l < TOTAL_RANK) {
#pragma unroll
        for (int dd = 0; dd < TOTAL_RANK; dd++) {
            float sgn = (__popc(dd & l) & 1) ? -1.0f : 1.0f;
            g_M[(b * TOTAL_RANK + dd) * TOTAL_RANK + l] =
                factor * sgn * (1.0f / 32.0f);
        }
    }
}

// ---------------------------------------------------------------------------
// Kernel 3: out[b,s,d] = sum_r rank_act[b,s,r] * M[b][d][r]
// One token per thread; each block covers 256 tokens of a single batch
// (4096 tokens/batch, 16 blocks per batch) -> M loads broadcast from shared.
// ---------------------------------------------------------------------------
__global__ __launch_bounds__(256) void k_out(const float* __restrict__ ra,
                                             float* __restrict__ out) {
    __shared__ float sM[TOTAL_RANK * TOTAL_RANK];
    int tid = threadIdx.x;
    int t   = blockIdx.x * 256 + tid;       // token id, 32768 total
    int b   = blockIdx.x >> 4;              // 16 blocks per batch

    if (tid < TOTAL_RANK * TOTAL_RANK)
        sM[tid] = g_M[b * TOTAL_RANK * TOTAL_RANK + tid];
    __syncthreads();

    const float4* ap = reinterpret_cast<const float4*>(ra) + (size_t)t * 4;
    float4 a0 = ap[0], a1 = ap[1], a2 = ap[2], a3 = ap[3];
    float av[16] = {a0.x, a0.y, a0.z, a0.w, a1.x, a1.y, a1.z, a1.w,
                    a2.x, a2.y, a2.z, a2.w, a3.x, a3.y, a3.z, a3.w};

    float o[16];
#pragma unroll
    for (int dd = 0; dd < 16; dd++) {
        float s = 0.f;
#pragma unroll
        for (int r = 0; r < 16; r++) s += av[r] * sM[dd * 16 + r];
        o[dd] = s;
    }
    float4* op = reinterpret_cast<float4*>(out) + (size_t)t * 4;
    op[0] = make_float4(o[0],  o[1],  o[2],  o[3]);
    op[1] = make_float4(o[4],  o[5],  o[6],  o[7]);
    op[2] = make_float4(o[8],  o[9],  o[10], o[11]);
    op[3] = make_float4(o[12], o[13], o[14], o[15]);
}

// ---------------------------------------------------------------------------
extern "C" void kernel_launch(void* const* d_in, const int* in_sizes, int n_in,
                              void* d_out, int out_size) {
    const float* hs    = (const float*)d_in[0];
    const float* ra    = (const float*)d_in[1];
    const float* W1    = (const float*)d_in[2];
    const float* b1    = (const float*)d_in[3];
    const float* gamma = (const float*)d_in[4];
    const float* beta  = (const float*)d_in[5];
    const float* W2    = (const float*)d_in[6];
    const float* b2    = (const float*)d_in[7];
    const float* ml    = (const float*)d_in[8];
    const float* rs    = (const float*)d_in[9];
    float* out = (float*)d_out;

    k_partial<<<BATCH * NCHUNK, 512>>>(hs);
    k_pool<<<32, 512>>>();
    k_x<<<BATCH, 256>>>(W1);
    k_ctrl<<<1, 256>>>(b1, gamma, beta, W2, b2, ml, rs);
    k_out<<<128, 256>>>(ra, out);
}